// round 9
// baseline (speedup 1.0000x reference)
#include <cuda_runtime.h>

#define NN 100000
#define EE 640000
#define GG 64
#define BN_EPS 1e-5f
#define SLOPE 0.01f
#define NB_SCAN 98   // ceil(100000/1024)
#define NCHUNK 1563  // ceil(100000/64)

// ---------------- scratch (static device buffers) ---------------------------
__device__ int   g_deg[NN];
__device__ float g_dinv[NN];
__device__ int   g_cnt[NN];
__device__ int   g_rowptr[NN + 1];
__device__ int   g_cursor[NN];
__device__ int   g_bsums[128];
__device__ int   g_boffs[130];
__device__ int   g_csr_src[EE];
__device__ float g_csr_w[EE];

__device__ __align__(16) float g_ZC[NN * 192];   // packed [Z0|Z1|Z2] per layer
__device__ __align__(16) float g_S [NN * 64];
__device__ __align__(16) float g_H1[NN * 64];
__device__ __align__(16) float g_H2[NN * 32];
__device__ __align__(16) float g_H3[NN * 16];

__device__ __align__(16) float g_Wc1[128 * 192];  // [f][ Wd | W1 | W2 ]
__device__ __align__(16) float g_Wc2[64 * 96];
__device__ __align__(16) float g_Wc3[32 * 48];
__device__ __align__(16) float g_sc1[64], g_sh1[64];
__device__ __align__(16) float g_sc2[32], g_sh2[32];
__device__ __align__(16) float g_sc3[16], g_sh3[16];

__device__ float g_pooled[GG * 16];
__device__ int   g_pcnt[GG];

// ---------------- f32x2 packed helpers -------------------------------------
__device__ __forceinline__ unsigned long long ffma2(unsigned long long a,
                                                    unsigned long long b,
                                                    unsigned long long c) {
    unsigned long long d;
    asm("fma.rn.f32x2 %0, %1, %2, %3;" : "=l"(d) : "l"(a), "l"(b), "l"(c));
    return d;
}
__device__ __forceinline__ unsigned long long dup2(float h) {
    unsigned long long r;
    unsigned hi = __float_as_uint(h);
    asm("mov.b64 %0, {%1, %1};" : "=l"(r) : "r"(hi));
    return r;
}
__device__ __forceinline__ void unpack2(unsigned long long v, float& lo, float& hi) {
    unsigned a, b;
    asm("mov.b64 {%0, %1}, %2;" : "=r"(a), "=r"(b) : "l"(v));
    lo = __uint_as_float(a);
    hi = __uint_as_float(b);
}

// ---------------- init ------------------------------------------------------
__global__ void k_zero() {
    int i = blockIdx.x * blockDim.x + threadIdx.x;
    if (i < NN) { g_deg[i] = 0; g_cnt[i] = 0; g_cursor[i] = 0; }
    if (i < GG * 16) g_pooled[i] = 0.f;
    if (i < GG) g_pcnt[i] = 0;
}

__global__ void k_count(const int* __restrict__ ei) {
    int e = blockIdx.x * blockDim.x + threadIdx.x;
    if (e >= EE) return;
    int s = ei[e], d = ei[EE + e];
    if (s != d) {
        atomicAdd(&g_deg[s], 1);
        atomicAdd(&g_cnt[d], 1);
    }
}

__global__ void k_dinv() {
    int i = blockIdx.x * blockDim.x + threadIdx.x;
    if (i < NN) g_dinv[i] = (g_deg[i] > 0) ? rsqrtf((float)g_deg[i]) : 0.f;
}

// ---------------- exclusive scan of g_cnt -> g_rowptr ----------------------
__global__ void k_scan1() {
    __shared__ int sm[1024];
    int t = threadIdx.x;
    int i = blockIdx.x * 1024 + t;
    int v = (i < NN) ? g_cnt[i] : 0;
    sm[t] = v;
    __syncthreads();
    for (int off = 1; off < 1024; off <<= 1) {
        int add = (t >= off) ? sm[t - off] : 0;
        __syncthreads();
        sm[t] += add;
        __syncthreads();
    }
    if (i < NN) g_rowptr[i] = sm[t] - v;
    if (t == 1023) g_bsums[blockIdx.x] = sm[1023];
}

__global__ void k_scan2(int nb) {
    __shared__ int sm[128];
    int t = threadIdx.x;
    int v = (t < nb) ? g_bsums[t] : 0;
    sm[t] = v;
    __syncthreads();
    for (int off = 1; off < 128; off <<= 1) {
        int add = (t >= off) ? sm[t - off] : 0;
        __syncthreads();
        sm[t] += add;
        __syncthreads();
    }
    if (t < nb) g_boffs[t] = sm[t] - v;
    if (t == nb - 1) g_boffs[nb] = sm[t];
}

__global__ void k_scan3(int nb) {
    int i = blockIdx.x * blockDim.x + threadIdx.x;
    if (i < NN) g_rowptr[i] += g_boffs[i >> 10];
    if (i == 0) g_rowptr[NN] = g_boffs[nb];
}

__global__ void k_fill(const int* __restrict__ ei) {
    int e = blockIdx.x * blockDim.x + threadIdx.x;
    if (e >= EE) return;
    int s = ei[e], d = ei[EE + e];
    if (s == d) return;
    float wv = -g_dinv[s] * g_dinv[d];
    int pos = g_rowptr[d] + atomicAdd(&g_cursor[d], 1);
    g_csr_src[pos] = s;
    g_csr_w[pos]   = wv;
}

// ---------------- prep: concatenated weights + BN affine fold ---------------
__global__ void k_prep(const float* __restrict__ W1, const float* __restrict__ W2,
                       const float* __restrict__ W3,
                       const float* __restrict__ b1, const float* __restrict__ gg1,
                       const float* __restrict__ be1, const float* __restrict__ m1,
                       const float* __restrict__ v1,
                       const float* __restrict__ b2, const float* __restrict__ gg2,
                       const float* __restrict__ be2, const float* __restrict__ m2,
                       const float* __restrict__ v2,
                       const float* __restrict__ b3, const float* __restrict__ gg3,
                       const float* __restrict__ be3, const float* __restrict__ m3,
                       const float* __restrict__ v3) {
    int i = blockIdx.x * blockDim.x + threadIdx.x;
    if (i < 24576) {                        // 128 x 192
        int f = i / 192, c = i % 192;
        int sec = c / 64, cc = c - sec * 64;
        int base = f * 64 + cc;
        float v = (sec == 0) ? (W1[base] - W1[16384 + base]) : W1[sec * 8192 + base];
        g_Wc1[i] = v;
    } else if (i < 24576 + 6144) {          // 64 x 96
        int j = i - 24576;
        int f = j / 96, c = j % 96;
        int sec = c / 32, cc = c - sec * 32;
        int base = f * 32 + cc;
        float v = (sec == 0) ? (W2[base] - W2[4096 + base]) : W2[sec * 2048 + base];
        g_Wc2[j] = v;
    } else if (i < 24576 + 6144 + 1536) {   // 32 x 48
        int j = i - 24576 - 6144;
        int f = j / 48, c = j % 48;
        int sec = c / 16, cc = c - sec * 16;
        int base = f * 16 + cc;
        float v = (sec == 0) ? (W3[base] - W3[1024 + base]) : W3[sec * 512 + base];
        g_Wc3[j] = v;
    } else if (i < 24576 + 6144 + 1536 + 64) {
        int o = i - (24576 + 6144 + 1536);
        float s = gg1[o] * rsqrtf(v1[o] + BN_EPS);
        g_sc1[o] = s;
        g_sh1[o] = be1[o] + (b1[o] - m1[o]) * s;
    } else if (i < 24576 + 6144 + 1536 + 64 + 32) {
        int o = i - (24576 + 6144 + 1536 + 64);
        float s = gg2[o] * rsqrtf(v2[o] + BN_EPS);
        g_sc2[o] = s;
        g_sh2[o] = be2[o] + (b2[o] - m2[o]) * s;
    } else if (i < 24576 + 6144 + 1536 + 64 + 32 + 16) {
        int o = i - (24576 + 6144 + 1536 + 64 + 32);
        float s = gg3[o] * rsqrtf(v3[o] + BN_EPS);
        g_sc3[o] = s;
        g_sh3[o] = be3[o] + (b3[o] - m3[o]) * s;
    }
}

// ---------------- persistent-W pipelined GEMM (single barrier per slab) -----
// ZC[N x 3Fout] = X[N x Fin] @ Wc.  W resident in smem for the whole kernel;
// blocks stride over 64-row chunks.  Double-buffered X slabs with exactly one
// __syncthreads per slab: STS(cur) -> sync -> compute(cur), while the next
// slab's LDG is already in flight.  Writing buf[(ki+1)&1] during compute of
// buf[ki&1] is race-free (disjoint buffers; KS even covers chunk hand-off).
template <int Fin, int Fout, int CT>
__global__ void __launch_bounds__(256)
k_gemm(const float* __restrict__ X, const float* __restrict__ Wc,
       float* __restrict__ ZC) {
    constexpr int N3    = 3 * Fout;
    constexpr int TC    = 6;             // N3 / CT
    constexpr int RT    = 256 / CT;
    constexpr int TR    = 64 / RT;       // rows per thread (8 / 4 / 2)
    constexpr int PAIRS = TR / 2;        // f32x2 row pairs (4 / 2 / 1)
    constexpr int KS    = Fin / 16;      // k slabs (even: 8 / 4 / 2)

    extern __shared__ float smem[];
    float* Ws = smem;                    // [Fin][N3]
    float* Xs = smem + Fin * N3;         // [2][16][64]

    int tid = threadIdx.x;
    int ct = tid % CT, rt = tid / CT;
    int tr0 = rt * TR;
    int tc0 = ct * TC;
    int sr  = tid & 63;                  // staging row
    int skq = tid >> 6;                  // staging k-quad 0..3

    // load W once
    for (int i = tid; i < Fin * N3 / 4; i += 256)
        *reinterpret_cast<float4*>(Ws + i * 4) =
            *reinterpret_cast<const float4*>(Wc + i * 4);
    __syncthreads();

    for (int chunk = blockIdx.x; chunk < NCHUNK; chunk += gridDim.x) {
        int row0 = chunk * 64;
        const float* xbase = X + (size_t)min(row0 + sr, NN - 1) * Fin;

        unsigned long long acc[PAIRS][TC];
#pragma unroll
        for (int p = 0; p < PAIRS; p++)
#pragma unroll
            for (int c = 0; c < TC; c++) acc[p][c] = 0ull;

        float4 xreg = *reinterpret_cast<const float4*>(xbase + skq * 4);

#pragma unroll
        for (int ki = 0; ki < KS; ki++) {
            float* Xb = Xs + (ki & 1) * 1024;
            Xb[(skq * 4 + 0) * 64 + sr] = xreg.x;
            Xb[(skq * 4 + 1) * 64 + sr] = xreg.y;
            Xb[(skq * 4 + 2) * 64 + sr] = xreg.z;
            Xb[(skq * 4 + 3) * 64 + sr] = xreg.w;
            if (ki + 1 < KS)     // prefetch next slab (hidden under compute)
                xreg = *reinterpret_cast<const float4*>(xbase + (ki + 1) * 16 + skq * 4);
            __syncthreads();     // single barrier per slab

            const float* Wrow = Ws + ki * 16 * N3 + tc0;
#pragma unroll
            for (int kk = 0; kk < 16; kk++) {
                const float* xrow = Xb + kk * 64 + tr0;
                unsigned long long xp[PAIRS];
                if constexpr (PAIRS == 4) {
                    ulonglong2 a = *reinterpret_cast<const ulonglong2*>(xrow);
                    ulonglong2 b = *reinterpret_cast<const ulonglong2*>(xrow + 4);
                    xp[0] = a.x; xp[1] = a.y; xp[2] = b.x; xp[3] = b.y;
                } else if constexpr (PAIRS == 2) {
                    ulonglong2 a = *reinterpret_cast<const ulonglong2*>(xrow);
                    xp[0] = a.x; xp[1] = a.y;
                } else {
                    xp[0] = *reinterpret_cast<const unsigned long long*>(xrow);
                }
                float wv[TC];
#pragma unroll
                for (int c = 0; c < TC; c += 2) {
                    float2 w2 = *reinterpret_cast<const float2*>(Wrow + kk * N3 + c);
                    wv[c] = w2.x; wv[c + 1] = w2.y;
                }
#pragma unroll
                for (int c = 0; c < TC; c++) {
                    unsigned long long wd = dup2(wv[c]);
#pragma unroll
                    for (int p = 0; p < PAIRS; p++)
                        acc[p][c] = ffma2(xp[p], wd, acc[p][c]);
                }
            }
        }

#pragma unroll
        for (int p = 0; p < PAIRS; p++) {
            int row = row0 + tr0 + 2 * p;
            float lo[TC], hi[TC];
#pragma unroll
            for (int c = 0; c < TC; c++) unpack2(acc[p][c], lo[c], hi[c]);
            if (row < NN) {
#pragma unroll
                for (int c = 0; c < TC; c++) ZC[(size_t)row * N3 + tc0 + c] = lo[c];
            }
            if (row + 1 < NN) {
#pragma unroll
                for (int c = 0; c < TC; c++) ZC[(size_t)(row + 1) * N3 + tc0 + c] = hi[c];
            }
        }
    }
}

// ---------------- props: predicated unroll-4 edge gather (MLP=4) ------------
// subgroup of LPN = F/4 lanes owns one edge stream; out-of-range slots load
// edge weight 0 so all 4 gathers are always issued (no dependent serial tail).

template <int F>
__device__ __forceinline__ float4 prop_gather(const float* __restrict__ Xg, int xs,
                                              int beg, int end, int sub, int fl,
                                              int EPW) {
    float4 a0 = make_float4(0.f, 0.f, 0.f, 0.f);
    float4 a1 = make_float4(0.f, 0.f, 0.f, 0.f);
    float4 a2 = make_float4(0.f, 0.f, 0.f, 0.f);
    float4 a3 = make_float4(0.f, 0.f, 0.f, 0.f);
    for (int base = beg + sub; base < end; base += 4 * EPW) {
        int i1 = base + EPW, i2 = base + 2 * EPW, i3 = base + 3 * EPW;
        bool p1 = i1 < end, p2 = i2 < end, p3 = i3 < end;
        int   s0 = g_csr_src[base];
        float w0 = g_csr_w[base];
        int   s1 = p1 ? g_csr_src[i1] : 0;
        float w1 = p1 ? g_csr_w[i1] : 0.f;
        int   s2 = p2 ? g_csr_src[i2] : 0;
        float w2 = p2 ? g_csr_w[i2] : 0.f;
        int   s3 = p3 ? g_csr_src[i3] : 0;
        float w3 = p3 ? g_csr_w[i3] : 0.f;
        float4 x0 = *reinterpret_cast<const float4*>(Xg + (size_t)s0 * xs + fl * 4);
        float4 x1 = *reinterpret_cast<const float4*>(Xg + (size_t)s1 * xs + fl * 4);
        float4 x2 = *reinterpret_cast<const float4*>(Xg + (size_t)s2 * xs + fl * 4);
        float4 x3 = *reinterpret_cast<const float4*>(Xg + (size_t)s3 * xs + fl * 4);
        a0.x += w0 * x0.x; a0.y += w0 * x0.y; a0.z += w0 * x0.z; a0.w += w0 * x0.w;
        a1.x += w1 * x1.x; a1.y += w1 * x1.y; a1.z += w1 * x1.z; a1.w += w1 * x1.w;
        a2.x += w2 * x2.x; a2.y += w2 * x2.y; a2.z += w2 * x2.z; a2.w += w2 * x2.w;
        a3.x += w3 * x3.x; a3.y += w3 * x3.y; a3.z += w3 * x3.z; a3.w += w3 * x3.w;
    }
    float4 acc;
    acc.x = (a0.x + a1.x) + (a2.x + a3.x);
    acc.y = (a0.y + a1.y) + (a2.y + a3.y);
    acc.z = (a0.z + a1.z) + (a2.z + a3.z);
    acc.w = (a0.w + a1.w) + (a2.w + a3.w);
    return acc;
}

// prop A: S = Z1 + 2 * (L_hat @ Z2)   (Z sections strided)
template <int F>
__global__ void k_propA(const float* __restrict__ Xg, int xs,
                        const float* __restrict__ Z1n, int zs,
                        float* __restrict__ S) {
    constexpr int LPN = F / 4;
    constexpr int EPW = 32 / LPN;
    int warp = (blockIdx.x * blockDim.x + threadIdx.x) >> 5;
    if (warp >= NN) return;
    int lane = threadIdx.x & 31;
    int sub = lane / LPN, fl = lane % LPN;
    int beg = g_rowptr[warp], end = g_rowptr[warp + 1];

    float4 acc = prop_gather<F>(Xg, xs, beg, end, sub, fl, EPW);
#pragma unroll
    for (int off = 16; off >= LPN; off >>= 1) {
        acc.x += __shfl_down_sync(0xffffffffu, acc.x, off);
        acc.y += __shfl_down_sync(0xffffffffu, acc.y, off);
        acc.z += __shfl_down_sync(0xffffffffu, acc.z, off);
        acc.w += __shfl_down_sync(0xffffffffu, acc.w, off);
    }
    if (sub == 0) {
        float4 z = *reinterpret_cast<const float4*>(Z1n + (size_t)warp * zs + fl * 4);
        float4 o;
        o.x = z.x + 2.f * acc.x; o.y = z.y + 2.f * acc.y;
        o.z = z.z + 2.f * acc.z; o.w = z.w + 2.f * acc.w;
        *reinterpret_cast<float4*>(S + (size_t)warp * F + fl * 4) = o;
    }
}

// prop B: H = lrelu( (Z0 + L_hat @ S) * scale + shift )
template <int F>
__global__ void k_propB(const float* __restrict__ Xg, int xs,
                        const float* __restrict__ Z0n, int zs,
                        const float* __restrict__ scale, const float* __restrict__ shift,
                        float* __restrict__ H) {
    constexpr int LPN = F / 4;
    constexpr int EPW = 32 / LPN;
    int warp = (blockIdx.x * blockDim.x + threadIdx.x) >> 5;
    if (warp >= NN) return;
    int lane = threadIdx.x & 31;
    int sub = lane / LPN, fl = lane % LPN;
    int beg = g_rowptr[warp], end = g_rowptr[warp + 1];

    float4 acc = prop_gather<F>(Xg, xs, beg, end, sub, fl, EPW);
#pragma unroll
    for (int off = 16; off >= LPN; off >>= 1) {
        acc.x += __shfl_down_sync(0xffffffffu, acc.x, off);
        acc.y += __shfl_down_sync(0xffffffffu, acc.y, off);
        acc.z += __shfl_down_sync(0xffffffffu, acc.z, off);
        acc.w += __shfl_down_sync(0xffffffffu, acc.w, off);
    }
    if (sub == 0) {
        float4 z  = *reinterpret_cast<const float4*>(Z0n + (size_t)warp * zs + fl * 4);
        float4 sc = *reinterpret_cast<const float4*>(scale + fl * 4);
        float4 sh = *reinterpret_cast<const float4*>(shift + fl * 4);
        float4 o;
        o.x = (z.x + acc.x) * sc.x + sh.x;
        o.y = (z.y + acc.y) * sc.y + sh.y;
        o.z = (z.z + acc.z) * sc.z + sh.z;
        o.w = (z.w + acc.w) * sc.w + sh.w;
        o.x = (o.x > 0.f) ? o.x : SLOPE * o.x;
        o.y = (o.y > 0.f) ? o.y : SLOPE * o.y;
        o.z = (o.z > 0.f) ? o.z : SLOPE * o.z;
        o.w = (o.w > 0.f) ? o.w : SLOPE * o.w;
        *reinterpret_cast<float4*>(H + (size_t)warp * F + fl * 4) = o;
    }
}

// ---------------- per-graph mean pool + head --------------------------------
#define PNODES 1024
__global__ void k_pool(const float* __restrict__ H, const int* __restrict__ batch) {
    __shared__ float ssum[GG * 16];
    __shared__ int   scnt[GG];
    for (int i = threadIdx.x; i < GG * 16; i += 256) ssum[i] = 0.f;
    for (int i = threadIdx.x; i < GG; i += 256) scnt[i] = 0;
    __syncthreads();

    int f   = threadIdx.x & 15;
    int sub = threadIdx.x >> 4;
    int base = blockIdx.x * PNODES;
    for (int n = sub; n < PNODES; n += 16) {
        int node = base + n;
        if (node >= NN) break;
        int b = batch[node];
        atomicAdd(&ssum[b * 16 + f], H[node * 16 + f]);
        if (f == 0) atomicAdd(&scnt[b], 1);
    }
    __syncthreads();
    for (int i = threadIdx.x; i < GG * 16; i += 256) atomicAdd(&g_pooled[i], ssum[i]);
    for (int i = threadIdx.x; i < GG; i += 256) atomicAdd(&g_pcnt[i], scnt[i]);
}

__global__ void k_final(const float* __restrict__ lw, const float* __restrict__ lb,
                        float* __restrict__ out) {
    int t = threadIdx.x;
    if (t >= GG * 2) return;
    int g = t >> 1, c = t & 1;
    float inv = 1.f / fmaxf((float)g_pcnt[g], 1.f);
    float s = 0.f;
#pragma unroll
    for (int f = 0; f < 16; f++) s += g_pooled[g * 16 + f] * lw[c * 16 + f];
    out[t] = s * inv + lb[c];
}

// ---------------- launch ----------------------------------------------------
extern "C" void kernel_launch(void* const* d_in, const int* in_sizes, int n_in,
                              void* d_out, int out_size) {
    const float* x     = (const float*)d_in[0];
    const int*   ei    = (const int*)  d_in[1];
    const int*   batch = (const int*)  d_in[2];
    const float* W1 = (const float*)d_in[3];
    const float* b1 = (const float*)d_in[4];
    const float* g1 = (const float*)d_in[5];
    const float* be1= (const float*)d_in[6];
    const float* m1 = (const float*)d_in[7];
    const float* v1 = (const float*)d_in[8];
    const float* W2 = (const float*)d_in[9];
    const float* b2 = (const float*)d_in[10];
    const float* g2 = (const float*)d_in[11];
    const float* be2= (const float*)d_in[12];
    const float* m2 = (const float*)d_in[13];
    const float* v2 = (const float*)d_in[14];
    const float* W3 = (const float*)d_in[15];
    const float* b3 = (const float*)d_in[16];
    const float* g3 = (const float*)d_in[17];
    const float* be3= (const float*)d_in[18];
    const float* m3 = (const float*)d_in[19];
    const float* v3 = (const float*)d_in[20];
    const float* lw = (const float*)d_in[21];
    const float* lb = (const float*)d_in[22];
    float* out = (float*)d_out;

    float *ZC, *S, *H1, *H2, *H3, *Wc1, *Wc2, *Wc3;
    float *sc1, *sh1, *sc2, *sh2, *sc3, *sh3;
    cudaGetSymbolAddress((void**)&ZC, g_ZC);
    cudaGetSymbolAddress((void**)&S,  g_S);
    cudaGetSymbolAddress((void**)&H1, g_H1);
    cudaGetSymbolAddress((void**)&H2, g_H2);
    cudaGetSymbolAddress((void**)&H3, g_H3);
    cudaGetSymbolAddress((void**)&Wc1, g_Wc1);
    cudaGetSymbolAddress((void**)&Wc2, g_Wc2);
    cudaGetSymbolAddress((void**)&Wc3, g_Wc3);
    cudaGetSymbolAddress((void**)&sc1, g_sc1);
    cudaGetSymbolAddress((void**)&sh1, g_sh1);
    cudaGetSymbolAddress((void**)&sc2, g_sc2);
    cudaGetSymbolAddress((void**)&sh2, g_sh2);
    cudaGetSymbolAddress((void**)&sc3, g_sc3);
    cudaGetSymbolAddress((void**)&sh3, g_sh3);

    // dynamic smem: W resident + 2 x (16x64) X slabs
    const int smem1 = (128 * 192 + 2 * 1024) * 4;   // 106496
    const int smem2 = (64 * 96 + 2 * 1024) * 4;     //  32768
    const int smem3 = (32 * 48 + 2 * 1024) * 4;     //  14336
    cudaFuncSetAttribute((const void*)k_gemm<128, 64, 32>,
                         cudaFuncAttributeMaxDynamicSharedMemorySize, smem1);
    cudaFuncSetAttribute((const void*)k_gemm<64, 32, 16>,
                         cudaFuncAttributeMaxDynamicSharedMemorySize, smem2);
    cudaFuncSetAttribute((const void*)k_gemm<32, 16, 8>,
                         cudaFuncAttributeMaxDynamicSharedMemorySize, smem3);

    const int TB = 256;
    const int GEMM_GRID = 296;   // quasi-persistent: 2 blocks per SM
    // launches 1-3: prelude (CSR-independent)
    k_zero <<<(NN + TB - 1) / TB, TB>>>();
    k_count<<<(EE + TB - 1) / TB, TB>>>(ei);
    k_prep <<<(24576 + 6144 + 1536 + 112 + TB - 1) / TB, TB>>>(
        W1, W2, W3, b1, g1, be1, m1, v1, b2, g2, be2, m2, v2, b3, g3, be3, m3, v3);

    // launch 4: layer-1 GEMM (profiled by ncu)
    k_gemm<128, 64, 32><<<GEMM_GRID, 256, smem1>>>(x, Wc1, ZC);

    // CSR build
    k_dinv <<<(NN + TB - 1) / TB, TB>>>();
    k_scan1<<<NB_SCAN, 1024>>>();
    k_scan2<<<1, 128>>>(NB_SCAN);
    k_scan3<<<(NN + TB - 1) / TB, TB>>>(NB_SCAN);
    k_fill <<<(EE + TB - 1) / TB, TB>>>(ei);

    int prop_grid = (NN * 32 + TB - 1) / TB;   // one warp per node

    // --- layer 1 props (sections of ZC: stride 192, offsets 0/64/128) ---
    k_propA<64><<<prop_grid, TB>>>(ZC + 128, 192, ZC + 64, 192, S);
    k_propB<64><<<prop_grid, TB>>>(S, 64, ZC, 192, sc1, sh1, H1);

    // --- layer 2: 64 -> 32 ---
    k_gemm<64, 32, 16><<<GEMM_GRID, 256, smem2>>>(H1, Wc2, ZC);
    k_propA<32><<<prop_grid, TB>>>(ZC + 64, 96, ZC + 32, 96, S);
    k_propB<32><<<prop_grid, TB>>>(S, 32, ZC, 96, sc2, sh2, H2);

    // --- layer 3: 32 -> 16 ---
    k_gemm<32, 16, 8><<<GEMM_GRID, 256, smem3>>>(H2, Wc3, ZC);
    k_propA<16><<<prop_grid, TB>>>(ZC + 32, 48, ZC + 16, 48, S);
    k_propB<16><<<prop_grid, TB>>>(S, 16, ZC, 48, sc3, sh3, H3);

    // --- pool + linear head ---
    k_pool <<<(NN + PNODES - 1) / PNODES, 256>>>(H3, batch);
    k_final<<<1, 128>>>(lw, lb, out);
}

// round 11
// speedup vs baseline: 1.1929x; 1.1929x over previous
#include <cuda_runtime.h>

#define NN 100000
#define EE 640000
#define GG 64
#define BN_EPS 1e-5f
#define SLOPE 0.01f
#define NB_SCAN 98   // ceil(100000/1024)
#define NCHUNK 1563  // ceil(100000/64)

// ---------------- scratch (static device buffers) ---------------------------
__device__ int   g_deg[NN];
__device__ float g_dinv[NN];
__device__ int   g_cnt[NN];
__device__ int   g_rowptr[NN + 1];
__device__ int   g_cursor[NN];
__device__ int   g_bsums[128];
__device__ int   g_boffs[130];
__device__ int   g_csr_src[EE];
__device__ float g_csr_w[EE];

__device__ __align__(16) float g_ZC[NN * 192];   // packed [Z0|Z1|Z2] per layer
__device__ __align__(16) float g_S [NN * 64];
__device__ __align__(16) float g_H1[NN * 64];
__device__ __align__(16) float g_H2[NN * 32];
__device__ __align__(16) float g_H3[NN * 16];

__device__ __align__(16) float g_Wc1[128 * 192];  // [f][ Wd | W1 | W2 ]
__device__ __align__(16) float g_Wc2[64 * 96];
__device__ __align__(16) float g_Wc3[32 * 48];
__device__ __align__(16) float g_sc1[64], g_sh1[64];
__device__ __align__(16) float g_sc2[32], g_sh2[32];
__device__ __align__(16) float g_sc3[16], g_sh3[16];

__device__ float g_pooled[GG * 16];
__device__ int   g_pcnt[GG];

// ---------------- f32x2 packed helpers -------------------------------------
__device__ __forceinline__ unsigned long long ffma2(unsigned long long a,
                                                    unsigned long long b,
                                                    unsigned long long c) {
    unsigned long long d;
    asm("fma.rn.f32x2 %0, %1, %2, %3;" : "=l"(d) : "l"(a), "l"(b), "l"(c));
    return d;
}
__device__ __forceinline__ unsigned long long dup2(float h) {
    unsigned long long r;
    unsigned hi = __float_as_uint(h);
    asm("mov.b64 %0, {%1, %1};" : "=l"(r) : "r"(hi));
    return r;
}
__device__ __forceinline__ void unpack2(unsigned long long v, float& lo, float& hi) {
    unsigned a, b;
    asm("mov.b64 {%0, %1}, %2;" : "=r"(a), "=r"(b) : "l"(v));
    lo = __uint_as_float(a);
    hi = __uint_as_float(b);
}

// ---------------- init ------------------------------------------------------
__global__ void k_zero() {
    int i = blockIdx.x * blockDim.x + threadIdx.x;
    if (i < NN) { g_deg[i] = 0; g_cnt[i] = 0; g_cursor[i] = 0; }
    if (i < GG * 16) g_pooled[i] = 0.f;
    if (i < GG) g_pcnt[i] = 0;
}

__global__ void k_count(const int* __restrict__ ei) {
    int e = blockIdx.x * blockDim.x + threadIdx.x;
    if (e >= EE) return;
    int s = ei[e], d = ei[EE + e];
    if (s != d) {
        atomicAdd(&g_deg[s], 1);
        atomicAdd(&g_cnt[d], 1);
    }
}

__global__ void k_dinv() {
    int i = blockIdx.x * blockDim.x + threadIdx.x;
    if (i < NN) g_dinv[i] = (g_deg[i] > 0) ? rsqrtf((float)g_deg[i]) : 0.f;
}

// ---------------- exclusive scan of g_cnt -> g_rowptr ----------------------
__global__ void k_scan1() {
    __shared__ int sm[1024];
    int t = threadIdx.x;
    int i = blockIdx.x * 1024 + t;
    int v = (i < NN) ? g_cnt[i] : 0;
    sm[t] = v;
    __syncthreads();
    for (int off = 1; off < 1024; off <<= 1) {
        int add = (t >= off) ? sm[t - off] : 0;
        __syncthreads();
        sm[t] += add;
        __syncthreads();
    }
    if (i < NN) g_rowptr[i] = sm[t] - v;
    if (t == 1023) g_bsums[blockIdx.x] = sm[1023];
}

__global__ void k_scan2(int nb) {
    __shared__ int sm[128];
    int t = threadIdx.x;
    int v = (t < nb) ? g_bsums[t] : 0;
    sm[t] = v;
    __syncthreads();
    for (int off = 1; off < 128; off <<= 1) {
        int add = (t >= off) ? sm[t - off] : 0;
        __syncthreads();
        sm[t] += add;
        __syncthreads();
    }
    if (t < nb) g_boffs[t] = sm[t] - v;
    if (t == nb - 1) g_boffs[nb] = sm[t];
}

__global__ void k_scan3(int nb) {
    int i = blockIdx.x * blockDim.x + threadIdx.x;
    if (i < NN) g_rowptr[i] += g_boffs[i >> 10];
    if (i == 0) g_rowptr[NN] = g_boffs[nb];
}

__global__ void k_fill(const int* __restrict__ ei) {
    int e = blockIdx.x * blockDim.x + threadIdx.x;
    if (e >= EE) return;
    int s = ei[e], d = ei[EE + e];
    if (s == d) return;
    float wv = -g_dinv[s] * g_dinv[d];
    int pos = g_rowptr[d] + atomicAdd(&g_cursor[d], 1);
    g_csr_src[pos] = s;
    g_csr_w[pos]   = wv;
}

// ---------------- prep: concatenated weights + BN affine fold ---------------
__global__ void k_prep(const float* __restrict__ W1, const float* __restrict__ W2,
                       const float* __restrict__ W3,
                       const float* __restrict__ b1, const float* __restrict__ gg1,
                       const float* __restrict__ be1, const float* __restrict__ m1,
                       const float* __restrict__ v1,
                       const float* __restrict__ b2, const float* __restrict__ gg2,
                       const float* __restrict__ be2, const float* __restrict__ m2,
                       const float* __restrict__ v2,
                       const float* __restrict__ b3, const float* __restrict__ gg3,
                       const float* __restrict__ be3, const float* __restrict__ m3,
                       const float* __restrict__ v3) {
    int i = blockIdx.x * blockDim.x + threadIdx.x;
    if (i < 24576) {                        // 128 x 192
        int f = i / 192, c = i % 192;
        int sec = c / 64, cc = c - sec * 64;
        int base = f * 64 + cc;
        float v = (sec == 0) ? (W1[base] - W1[16384 + base]) : W1[sec * 8192 + base];
        g_Wc1[i] = v;
    } else if (i < 24576 + 6144) {          // 64 x 96
        int j = i - 24576;
        int f = j / 96, c = j % 96;
        int sec = c / 32, cc = c - sec * 32;
        int base = f * 32 + cc;
        float v = (sec == 0) ? (W2[base] - W2[4096 + base]) : W2[sec * 2048 + base];
        g_Wc2[j] = v;
    } else if (i < 24576 + 6144 + 1536) {   // 32 x 48
        int j = i - 24576 - 6144;
        int f = j / 48, c = j % 48;
        int sec = c / 16, cc = c - sec * 16;
        int base = f * 16 + cc;
        float v = (sec == 0) ? (W3[base] - W3[1024 + base]) : W3[sec * 512 + base];
        g_Wc3[j] = v;
    } else if (i < 24576 + 6144 + 1536 + 64) {
        int o = i - (24576 + 6144 + 1536);
        float s = gg1[o] * rsqrtf(v1[o] + BN_EPS);
        g_sc1[o] = s;
        g_sh1[o] = be1[o] + (b1[o] - m1[o]) * s;
    } else if (i < 24576 + 6144 + 1536 + 64 + 32) {
        int o = i - (24576 + 6144 + 1536 + 64);
        float s = gg2[o] * rsqrtf(v2[o] + BN_EPS);
        g_sc2[o] = s;
        g_sh2[o] = be2[o] + (b2[o] - m2[o]) * s;
    } else if (i < 24576 + 6144 + 1536 + 64 + 32 + 16) {
        int o = i - (24576 + 6144 + 1536 + 64 + 32);
        float s = gg3[o] * rsqrtf(v3[o] + BN_EPS);
        g_sc3[o] = s;
        g_sh3[o] = be3[o] + (b3[o] - m3[o]) * s;
    }
}

// ---------------- persistent-W pipelined GEMM (strided column map) ----------
// ZC[N x 3Fout] = X[N x Fin] @ Wc.  W resident in smem; blocks stride over
// 64-row chunks; double-buffered transposed X slabs, one barrier per slab.
// Thread ct handles columns {c*CT + ct, c=0..5}: each W load is a dense
// lane-stride-4B LDS.32 -> 1 smem wavefront (vs 6 for the contiguous map).
// X pair loads are warp-broadcast.  smem wf/warp/kk: 8 vs 20 before -> the
// kernel flips from smem-wavefront-bound to FMA-pipe-bound.
template <int Fin, int Fout, int CT>
__global__ void __launch_bounds__(256)
k_gemm(const float* __restrict__ X, const float* __restrict__ Wc,
       float* __restrict__ ZC) {
    constexpr int N3    = 3 * Fout;
    constexpr int TC    = 6;             // N3 / CT
    constexpr int RT    = 256 / CT;
    constexpr int TR    = 64 / RT;       // rows per thread (8 / 4 / 2)
    constexpr int PAIRS = TR / 2;        // f32x2 row pairs (4 / 2 / 1)
    constexpr int KS    = Fin / 16;      // k slabs (even: 8 / 4 / 2)

    extern __shared__ float smem[];
    float* Ws = smem;                    // [Fin][N3]
    float* Xs = smem + Fin * N3;         // [2][16][64]

    int tid = threadIdx.x;
    int ct = tid % CT, rt = tid / CT;
    int tr0 = rt * TR;
    int sr  = tid & 63;                  // staging row
    int skq = tid >> 6;                  // staging k-quad 0..3

    // load W once
    for (int i = tid; i < Fin * N3 / 4; i += 256)
        *reinterpret_cast<float4*>(Ws + i * 4) =
            *reinterpret_cast<const float4*>(Wc + i * 4);
    __syncthreads();

    for (int chunk = blockIdx.x; chunk < NCHUNK; chunk += gridDim.x) {
        int row0 = chunk * 64;
        const float* xbase = X + (size_t)min(row0 + sr, NN - 1) * Fin;

        unsigned long long acc[PAIRS][TC];
#pragma unroll
        for (int p = 0; p < PAIRS; p++)
#pragma unroll
            for (int c = 0; c < TC; c++) acc[p][c] = 0ull;

        float4 xreg = *reinterpret_cast<const float4*>(xbase + skq * 4);

#pragma unroll
        for (int ki = 0; ki < KS; ki++) {
            float* Xb = Xs + (ki & 1) * 1024;
            Xb[(skq * 4 + 0) * 64 + sr] = xreg.x;
            Xb[(skq * 4 + 1) * 64 + sr] = xreg.y;
            Xb[(skq * 4 + 2) * 64 + sr] = xreg.z;
            Xb[(skq * 4 + 3) * 64 + sr] = xreg.w;
            if (ki + 1 < KS)     // prefetch next slab (hidden under compute)
                xreg = *reinterpret_cast<const float4*>(xbase + (ki + 1) * 16 + skq * 4);
            __syncthreads();     // single barrier per slab

            const float* Wrow = Ws + ki * 16 * N3 + ct;
#pragma unroll
            for (int kk = 0; kk < 16; kk++) {
                const float* xrow = Xb + kk * 64 + tr0;
                unsigned long long xp[PAIRS];
                if constexpr (PAIRS == 4) {
                    ulonglong2 a = *reinterpret_cast<const ulonglong2*>(xrow);
                    ulonglong2 b = *reinterpret_cast<const ulonglong2*>(xrow + 4);
                    xp[0] = a.x; xp[1] = a.y; xp[2] = b.x; xp[3] = b.y;
                } else if constexpr (PAIRS == 2) {
                    ulonglong2 a = *reinterpret_cast<const ulonglong2*>(xrow);
                    xp[0] = a.x; xp[1] = a.y;
                } else {
                    xp[0] = *reinterpret_cast<const unsigned long long*>(xrow);
                }
                // dense W loads: lane ct reads col c*CT+ct (stride-4B per lane)
                float wv[TC];
#pragma unroll
                for (int c = 0; c < TC; c++) wv[c] = Wrow[kk * N3 + c * CT];
#pragma unroll
                for (int c = 0; c < TC; c++) {
                    unsigned long long wd = dup2(wv[c]);
#pragma unroll
                    for (int p = 0; p < PAIRS; p++)
                        acc[p][c] = ffma2(xp[p], wd, acc[p][c]);
                }
            }
        }

#pragma unroll
        for (int p = 0; p < PAIRS; p++) {
            int row = row0 + tr0 + 2 * p;
            float lo[TC], hi[TC];
#pragma unroll
            for (int c = 0; c < TC; c++) unpack2(acc[p][c], lo[c], hi[c]);
            if (row < NN) {
#pragma unroll
                for (int c = 0; c < TC; c++)
                    ZC[(size_t)row * N3 + c * CT + ct] = lo[c];
            }
            if (row + 1 < NN) {
#pragma unroll
                for (int c = 0; c < TC; c++)
                    ZC[(size_t)(row + 1) * N3 + c * CT + ct] = hi[c];
            }
        }
    }
}

// ---------------- props: one warp per node, unroll-2 edge loop (MLP=2) -----
// prop A: S = Z1 + 2 * (L_hat @ Z2)   (Z sections strided)
template <int F>
__global__ void k_propA(const float* __restrict__ Xg, int xs,
                        const float* __restrict__ Z1n, int zs,
                        float* __restrict__ S) {
    constexpr int LPN = F / 4;
    constexpr int EPW = 32 / LPN;
    int warp = (blockIdx.x * blockDim.x + threadIdx.x) >> 5;
    if (warp >= NN) return;
    int lane = threadIdx.x & 31;
    int sub = lane / LPN, fl = lane % LPN;
    int beg = g_rowptr[warp], end = g_rowptr[warp + 1];

    float4 a0 = make_float4(0.f, 0.f, 0.f, 0.f);
    float4 a1 = make_float4(0.f, 0.f, 0.f, 0.f);
    int idx = beg + sub;
    for (; idx + EPW < end; idx += 2 * EPW) {
        int s0 = g_csr_src[idx],       s1 = g_csr_src[idx + EPW];
        float w0 = g_csr_w[idx],       w1 = g_csr_w[idx + EPW];
        float4 x0 = *reinterpret_cast<const float4*>(Xg + (size_t)s0 * xs + fl * 4);
        float4 x1 = *reinterpret_cast<const float4*>(Xg + (size_t)s1 * xs + fl * 4);
        a0.x += w0 * x0.x; a0.y += w0 * x0.y; a0.z += w0 * x0.z; a0.w += w0 * x0.w;
        a1.x += w1 * x1.x; a1.y += w1 * x1.y; a1.z += w1 * x1.z; a1.w += w1 * x1.w;
    }
    if (idx < end) {
        int s0 = g_csr_src[idx];
        float w0 = g_csr_w[idx];
        float4 x0 = *reinterpret_cast<const float4*>(Xg + (size_t)s0 * xs + fl * 4);
        a0.x += w0 * x0.x; a0.y += w0 * x0.y; a0.z += w0 * x0.z; a0.w += w0 * x0.w;
    }
    float4 acc;
    acc.x = a0.x + a1.x; acc.y = a0.y + a1.y;
    acc.z = a0.z + a1.z; acc.w = a0.w + a1.w;
#pragma unroll
    for (int off = 16; off >= LPN; off >>= 1) {
        acc.x += __shfl_down_sync(0xffffffffu, acc.x, off);
        acc.y += __shfl_down_sync(0xffffffffu, acc.y, off);
        acc.z += __shfl_down_sync(0xffffffffu, acc.z, off);
        acc.w += __shfl_down_sync(0xffffffffu, acc.w, off);
    }
    if (sub == 0) {
        float4 z = *reinterpret_cast<const float4*>(Z1n + (size_t)warp * zs + fl * 4);
        float4 o;
        o.x = z.x + 2.f * acc.x; o.y = z.y + 2.f * acc.y;
        o.z = z.z + 2.f * acc.z; o.w = z.w + 2.f * acc.w;
        *reinterpret_cast<float4*>(S + (size_t)warp * F + fl * 4) = o;
    }
}

// prop B: H = lrelu( (Z0 + L_hat @ S) * scale + shift )
template <int F>
__global__ void k_propB(const float* __restrict__ Xg, int xs,
                        const float* __restrict__ Z0n, int zs,
                        const float* __restrict__ scale, const float* __restrict__ shift,
                        float* __restrict__ H) {
    constexpr int LPN = F / 4;
    constexpr int EPW = 32 / LPN;
    int warp = (blockIdx.x * blockDim.x + threadIdx.x) >> 5;
    if (warp >= NN) return;
    int lane = threadIdx.x & 31;
    int sub = lane / LPN, fl = lane % LPN;
    int beg = g_rowptr[warp], end = g_rowptr[warp + 1];

    float4 a0 = make_float4(0.f, 0.f, 0.f, 0.f);
    float4 a1 = make_float4(0.f, 0.f, 0.f, 0.f);
    int idx = beg + sub;
    for (; idx + EPW < end; idx += 2 * EPW) {
        int s0 = g_csr_src[idx],       s1 = g_csr_src[idx + EPW];
        float w0 = g_csr_w[idx],       w1 = g_csr_w[idx + EPW];
        float4 x0 = *reinterpret_cast<const float4*>(Xg + (size_t)s0 * xs + fl * 4);
        float4 x1 = *reinterpret_cast<const float4*>(Xg + (size_t)s1 * xs + fl * 4);
        a0.x += w0 * x0.x; a0.y += w0 * x0.y; a0.z += w0 * x0.z; a0.w += w0 * x0.w;
        a1.x += w1 * x1.x; a1.y += w1 * x1.y; a1.z += w1 * x1.z; a1.w += w1 * x1.w;
    }
    if (idx < end) {
        int s0 = g_csr_src[idx];
        float w0 = g_csr_w[idx];
        float4 x0 = *reinterpret_cast<const float4*>(Xg + (size_t)s0 * xs + fl * 4);
        a0.x += w0 * x0.x; a0.y += w0 * x0.y; a0.z += w0 * x0.z; a0.w += w0 * x0.w;
    }
    float4 acc;
    acc.x = a0.x + a1.x; acc.y = a0.y + a1.y;
    acc.z = a0.z + a1.z; acc.w = a0.w + a1.w;
#pragma unroll
    for (int off = 16; off >= LPN; off >>= 1) {
        acc.x += __shfl_down_sync(0xffffffffu, acc.x, off);
        acc.y += __shfl_down_sync(0xffffffffu, acc.y, off);
        acc.z += __shfl_down_sync(0xffffffffu, acc.z, off);
        acc.w += __shfl_down_sync(0xffffffffu, acc.w, off);
    }
    if (sub == 0) {
        float4 z  = *reinterpret_cast<const float4*>(Z0n + (size_t)warp * zs + fl * 4);
        float4 sc = *reinterpret_cast<const float4*>(scale + fl * 4);
        float4 sh = *reinterpret_cast<const float4*>(shift + fl * 4);
        float4 o;
        o.x = (z.x + acc.x) * sc.x + sh.x;
        o.y = (z.y + acc.y) * sc.y + sh.y;
        o.z = (z.z + acc.z) * sc.z + sh.z;
        o.w = (z.w + acc.w) * sc.w + sh.w;
        o.x = (o.x > 0.f) ? o.x : SLOPE * o.x;
        o.y = (o.y > 0.f) ? o.y : SLOPE * o.y;
        o.z = (o.z > 0.f) ? o.z : SLOPE * o.z;
        o.w = (o.w > 0.f) ? o.w : SLOPE * o.w;
        *reinterpret_cast<float4*>(H + (size_t)warp * F + fl * 4) = o;
    }
}

// ---------------- per-graph mean pool + head --------------------------------
#define PNODES 1024
__global__ void k_pool(const float* __restrict__ H, const int* __restrict__ batch) {
    __shared__ float ssum[GG * 16];
    __shared__ int   scnt[GG];
    for (int i = threadIdx.x; i < GG * 16; i += 256) ssum[i] = 0.f;
    for (int i = threadIdx.x; i < GG; i += 256) scnt[i] = 0;
    __syncthreads();

    int f   = threadIdx.x & 15;
    int sub = threadIdx.x >> 4;
    int base = blockIdx.x * PNODES;
    for (int n = sub; n < PNODES; n += 16) {
        int node = base + n;
        if (node >= NN) break;
        int b = batch[node];
        atomicAdd(&ssum[b * 16 + f], H[node * 16 + f]);
        if (f == 0) atomicAdd(&scnt[b], 1);
    }
    __syncthreads();
    for (int i = threadIdx.x; i < GG * 16; i += 256) atomicAdd(&g_pooled[i], ssum[i]);
    for (int i = threadIdx.x; i < GG; i += 256) atomicAdd(&g_pcnt[i], scnt[i]);
}

__global__ void k_final(const float* __restrict__ lw, const float* __restrict__ lb,
                        float* __restrict__ out) {
    int t = threadIdx.x;
    if (t >= GG * 2) return;
    int g = t >> 1, c = t & 1;
    float inv = 1.f / fmaxf((float)g_pcnt[g], 1.f);
    float s = 0.f;
#pragma unroll
    for (int f = 0; f < 16; f++) s += g_pooled[g * 16 + f] * lw[c * 16 + f];
    out[t] = s * inv + lb[c];
}

// ---------------- launch ----------------------------------------------------
extern "C" void kernel_launch(void* const* d_in, const int* in_sizes, int n_in,
                              void* d_out, int out_size) {
    const float* x     = (const float*)d_in[0];
    const int*   ei    = (const int*)  d_in[1];
    const int*   batch = (const int*)  d_in[2];
    const float* W1 = (const float*)d_in[3];
    const float* b1 = (const float*)d_in[4];
    const float* g1 = (const float*)d_in[5];
    const float* be1= (const float*)d_in[6];
    const float* m1 = (const float*)d_in[7];
    const float* v1 = (const float*)d_in[8];
    const float* W2 = (const float*)d_in[9];
    const float* b2 = (const float*)d_in[10];
    const float* g2 = (const float*)d_in[11];
    const float* be2= (const float*)d_in[12];
    const float* m2 = (const float*)d_in[13];
    const float* v2 = (const float*)d_in[14];
    const float* W3 = (const float*)d_in[15];
    const float* b3 = (const float*)d_in[16];
    const float* g3 = (const float*)d_in[17];
    const float* be3= (const float*)d_in[18];
    const float* m3 = (const float*)d_in[19];
    const float* v3 = (const float*)d_in[20];
    const float* lw = (const float*)d_in[21];
    const float* lb = (const float*)d_in[22];
    float* out = (float*)d_out;

    float *ZC, *S, *H1, *H2, *H3, *Wc1, *Wc2, *Wc3;
    float *sc1, *sh1, *sc2, *sh2, *sc3, *sh3;
    cudaGetSymbolAddress((void**)&ZC, g_ZC);
    cudaGetSymbolAddress((void**)&S,  g_S);
    cudaGetSymbolAddress((void**)&H1, g_H1);
    cudaGetSymbolAddress((void**)&H2, g_H2);
    cudaGetSymbolAddress((void**)&H3, g_H3);
    cudaGetSymbolAddress((void**)&Wc1, g_Wc1);
    cudaGetSymbolAddress((void**)&Wc2, g_Wc2);
    cudaGetSymbolAddress((void**)&Wc3, g_Wc3);
    cudaGetSymbolAddress((void**)&sc1, g_sc1);
    cudaGetSymbolAddress((void**)&sh1, g_sh1);
    cudaGetSymbolAddress((void**)&sc2, g_sc2);
    cudaGetSymbolAddress((void**)&sh2, g_sh2);
    cudaGetSymbolAddress((void**)&sc3, g_sc3);
    cudaGetSymbolAddress((void**)&sh3, g_sh3);

    // dynamic smem: W resident + 2 x (16x64) X slabs
    const int smem1 = (128 * 192 + 2 * 1024) * 4;   // 106496
    const int smem2 = (64 * 96 + 2 * 1024) * 4;     //  32768
    const int smem3 = (32 * 48 + 2 * 1024) * 4;     //  14336
    cudaFuncSetAttribute((const void*)k_gemm<128, 64, 32>,
                         cudaFuncAttributeMaxDynamicSharedMemorySize, smem1);
    cudaFuncSetAttribute((const void*)k_gemm<64, 32, 16>,
                         cudaFuncAttributeMaxDynamicSharedMemorySize, smem2);
    cudaFuncSetAttribute((const void*)k_gemm<32, 16, 8>,
                         cudaFuncAttributeMaxDynamicSharedMemorySize, smem3);

    const int TB = 256;
    const int GEMM_GRID = 296;   // quasi-persistent: 2 blocks per SM
    // launches 1-3: prelude (CSR-independent)
    k_zero <<<(NN + TB - 1) / TB, TB>>>();
    k_count<<<(EE + TB - 1) / TB, TB>>>(ei);
    k_prep <<<(24576 + 6144 + 1536 + 112 + TB - 1) / TB, TB>>>(
        W1, W2, W3, b1, g1, be1, m1, v1, b2, g2, be2, m2, v2, b3, g3, be3, m3, v3);

    // launch 4: layer-1 GEMM (profiled by ncu)
    k_gemm<128, 64, 32><<<GEMM_GRID, 256, smem1>>>(x, Wc1, ZC);

    // CSR build
    k_dinv <<<(NN + TB - 1) / TB, TB>>>();
    k_scan1<<<NB_SCAN, 1024>>>();
    k_scan2<<<1, 128>>>(NB_SCAN);
    k_scan3<<<(NN + TB - 1) / TB, TB>>>(NB_SCAN);
    k_fill <<<(EE + TB - 1) / TB, TB>>>(ei);

    int prop_grid = (NN * 32 + TB - 1) / TB;   // one warp per node

    // --- layer 1 props (sections of ZC: stride 192, offsets 0/64/128) ---
    k_propA<64><<<prop_grid, TB>>>(ZC + 128, 192, ZC + 64, 192, S);
    k_propB<64><<<prop_grid, TB>>>(S, 64, ZC, 192, sc1, sh1, H1);

    // --- layer 2: 64 -> 32 ---
    k_gemm<64, 32, 16><<<GEMM_GRID, 256, smem2>>>(H1, Wc2, ZC);
    k_propA<32><<<prop_grid, TB>>>(ZC + 64, 96, ZC + 32, 96, S);
    k_propB<32><<<prop_grid, TB>>>(S, 32, ZC, 96, sc2, sh2, H2);

    // --- layer 3: 32 -> 16 ---
    k_gemm<32, 16, 8><<<GEMM_GRID, 256, smem3>>>(H2, Wc3, ZC);
    k_propA<16><<<prop_grid, TB>>>(ZC + 32, 48, ZC + 16, 48, S);
    k_propB<16><<<prop_grid, TB>>>(S, 16, ZC, 48, sc3, sh3, H3);

    // --- pool + linear head ---
    k_pool <<<(NN + PNODES - 1) / PNODES, 256>>>(H3, batch);
    k_final<<<1, 128>>>(lw, lb, out);
}

// round 13
// speedup vs baseline: 1.2205x; 1.0231x over previous
#include <cuda_runtime.h>

#define NN 100000
#define EE 640000
#define GG 64
#define BN_EPS 1e-5f
#define SLOPE 0.01f
#define NB_SCAN 98   // ceil(100000/1024)

// ---------------- scratch (static device buffers) ---------------------------
__device__ int   g_deg[NN];
__device__ float g_dinv[NN];
__device__ int   g_cnt[NN];
__device__ int   g_rowptr[NN + 1];
__device__ int   g_cursor[NN];
__device__ int   g_bsums[128];
__device__ int   g_boffs[130];
__device__ int   g_csr_src[EE];
__device__ float g_csr_w[EE];

__device__ __align__(16) float g_ZC[NN * 192];   // packed [Z0|Z1|Z2] per layer
__device__ __align__(16) float g_S [NN * 64];
__device__ __align__(16) float g_H1[NN * 64];
__device__ __align__(16) float g_H2[NN * 32];
__device__ __align__(16) float g_H3[NN * 16];

__device__ __align__(16) float g_Wc1[128 * 192];  // [f][ Wd | W1 | W2 ]
__device__ __align__(16) float g_Wc2[64 * 96];
__device__ __align__(16) float g_Wc3[32 * 48];
__device__ __align__(16) float g_sc1[64], g_sh1[64];
__device__ __align__(16) float g_sc2[32], g_sh2[32];
__device__ __align__(16) float g_sc3[16], g_sh3[16];

__device__ float g_pooled[GG * 16];
__device__ int   g_pcnt[GG];

// ---------------- f32x2 packed helpers -------------------------------------
__device__ __forceinline__ unsigned long long ffma2(unsigned long long a,
                                                    unsigned long long b,
                                                    unsigned long long c) {
    unsigned long long d;
    asm("fma.rn.f32x2 %0, %1, %2, %3;" : "=l"(d) : "l"(a), "l"(b), "l"(c));
    return d;
}
__device__ __forceinline__ unsigned long long dup2(float h) {
    unsigned long long r;
    unsigned hi = __float_as_uint(h);
    asm("mov.b64 %0, {%1, %1};" : "=l"(r) : "r"(hi));
    return r;
}
__device__ __forceinline__ void unpack2(unsigned long long v, float& lo, float& hi) {
    unsigned a, b;
    asm("mov.b64 {%0, %1}, %2;" : "=r"(a), "=r"(b) : "l"(v));
    lo = __uint_as_float(a);
    hi = __uint_as_float(b);
}

// ---------------- init ------------------------------------------------------
__global__ void k_zero() {
    int i = blockIdx.x * blockDim.x + threadIdx.x;
    if (i < NN) { g_deg[i] = 0; g_cnt[i] = 0; g_cursor[i] = 0; }
    if (i < GG * 16) g_pooled[i] = 0.f;
    if (i < GG) g_pcnt[i] = 0;
}

__global__ void k_count(const int* __restrict__ ei) {
    int e = blockIdx.x * blockDim.x + threadIdx.x;
    if (e >= EE) return;
    int s = ei[e], d = ei[EE + e];
    if (s != d) {
        atomicAdd(&g_deg[s], 1);
        atomicAdd(&g_cnt[d], 1);
    }
}

// ---------------- exclusive scan of g_cnt -> g_rowptr (+ dinv fused) -------
__global__ void k_scan1() {
    __shared__ int sm[1024];
    int t = threadIdx.x;
    int i = blockIdx.x * 1024 + t;
    int v = (i < NN) ? g_cnt[i] : 0;
    if (i < NN) {   // fused dinv (g_deg final after k_count)
        int dg = g_deg[i];
        g_dinv[i] = (dg > 0) ? rsqrtf((float)dg) : 0.f;
    }
    sm[t] = v;
    __syncthreads();
    for (int off = 1; off < 1024; off <<= 1) {
        int add = (t >= off) ? sm[t - off] : 0;
        __syncthreads();
        sm[t] += add;
        __syncthreads();
    }
    if (i < NN) g_rowptr[i] = sm[t] - v;
    if (t == 1023) g_bsums[blockIdx.x] = sm[1023];
}

__global__ void k_scan2(int nb) {
    __shared__ int sm[128];
    int t = threadIdx.x;
    int v = (t < nb) ? g_bsums[t] : 0;
    sm[t] = v;
    __syncthreads();
    for (int off = 1; off < 128; off <<= 1) {
        int add = (t >= off) ? sm[t - off] : 0;
        __syncthreads();
        sm[t] += add;
        __syncthreads();
    }
    if (t < nb) g_boffs[t] = sm[t] - v;
    if (t == nb - 1) g_boffs[nb] = sm[t];
}

__global__ void k_scan3(int nb) {
    int i = blockIdx.x * blockDim.x + threadIdx.x;
    if (i < NN) g_rowptr[i] += g_boffs[i >> 10];
    if (i == 0) g_rowptr[NN] = g_boffs[nb];
}

__global__ void k_fill(const int* __restrict__ ei) {
    int e = blockIdx.x * blockDim.x + threadIdx.x;
    if (e >= EE) return;
    int s = ei[e], d = ei[EE + e];
    if (s == d) return;
    float wv = -g_dinv[s] * g_dinv[d];
    int pos = g_rowptr[d] + atomicAdd(&g_cursor[d], 1);
    g_csr_src[pos] = s;
    g_csr_w[pos]   = wv;
}

// ---------------- prep: concatenated weights + BN affine fold ---------------
__global__ void k_prep(const float* __restrict__ W1, const float* __restrict__ W2,
                       const float* __restrict__ W3,
                       const float* __restrict__ b1, const float* __restrict__ gg1,
                       const float* __restrict__ be1, const float* __restrict__ m1,
                       const float* __restrict__ v1,
                       const float* __restrict__ b2, const float* __restrict__ gg2,
                       const float* __restrict__ be2, const float* __restrict__ m2,
                       const float* __restrict__ v2,
                       const float* __restrict__ b3, const float* __restrict__ gg3,
                       const float* __restrict__ be3, const float* __restrict__ m3,
                       const float* __restrict__ v3) {
    int i = blockIdx.x * blockDim.x + threadIdx.x;
    if (i < 24576) {                        // 128 x 192
        int f = i / 192, c = i % 192;
        int sec = c / 64, cc = c - sec * 64;
        int base = f * 64 + cc;
        float v = (sec == 0) ? (W1[base] - W1[16384 + base]) : W1[sec * 8192 + base];
        g_Wc1[i] = v;
    } else if (i < 24576 + 6144) {          // 64 x 96
        int j = i - 24576;
        int f = j / 96, c = j % 96;
        int sec = c / 32, cc = c - sec * 32;
        int base = f * 32 + cc;
        float v = (sec == 0) ? (W2[base] - W2[4096 + base]) : W2[sec * 2048 + base];
        g_Wc2[j] = v;
    } else if (i < 24576 + 6144 + 1536) {   // 32 x 48
        int j = i - 24576 - 6144;
        int f = j / 48, c = j % 48;
        int sec = c / 16, cc = c - sec * 16;
        int base = f * 16 + cc;
        float v = (sec == 0) ? (W3[base] - W3[1024 + base]) : W3[sec * 512 + base];
        g_Wc3[j] = v;
    } else if (i < 24576 + 6144 + 1536 + 64) {
        int o = i - (24576 + 6144 + 1536);
        float s = gg1[o] * rsqrtf(v1[o] + BN_EPS);
        g_sc1[o] = s;
        g_sh1[o] = be1[o] + (b1[o] - m1[o]) * s;
    } else if (i < 24576 + 6144 + 1536 + 64 + 32) {
        int o = i - (24576 + 6144 + 1536 + 64);
        float s = gg2[o] * rsqrtf(v2[o] + BN_EPS);
        g_sc2[o] = s;
        g_sh2[o] = be2[o] + (b2[o] - m2[o]) * s;
    } else if (i < 24576 + 6144 + 1536 + 64 + 32 + 16) {
        int o = i - (24576 + 6144 + 1536 + 64 + 32);
        float s = gg3[o] * rsqrtf(v3[o] + BN_EPS);
        g_sc3[o] = s;
        g_sh3[o] = be3[o] + (b3[o] - m3[o]) * s;
    }
}

// ---------------- persistent-W pipelined GEMM -------------------------------
// ZC[N x 3Fout] = X[N x Fin] @ Wc.  W resident in smem; blocks stride over
// BR-row chunks; double-buffered transposed X slabs, one barrier per slab.
// Strided column map (thread ct owns cols {c*CT+ct}) keeps W LDS lane-dense.
// All layers use TR=8 rows / PAIRS=4 f32x2 pairs per thread so the per-kk
// FMA:LDS ratio stays fma-bound.  Inner kk loop is manually software-
// pipelined (double register buffer for W scalars + X pairs) so the 29-cyc
// LDS latency is covered by a full kk block of FMA issue.
template <int Fin, int Fout, int CT, int BR>
__global__ void __launch_bounds__(256)
k_gemm(const float* __restrict__ X, const float* __restrict__ Wc,
       float* __restrict__ ZC) {
    constexpr int N3     = 3 * Fout;
    constexpr int TC     = 6;                 // N3 / CT
    constexpr int RT     = 256 / CT;
    constexpr int TR     = BR / RT;           // 8 for all layers
    constexpr int PAIRS  = TR / 2;            // 4
    constexpr int KS     = Fin / 16;          // k slabs (even)
    constexpr int PER    = (BR * 4) / 256;    // staged float4s per thread
    constexpr int NCHK   = (NN + BR - 1) / BR;

    extern __shared__ float smem[];
    float* Ws = smem;                         // [Fin][N3]
    float* Xs = smem + Fin * N3;              // [2][16][BR]

    int tid = threadIdx.x;
    int ct = tid % CT, rt = tid / CT;
    int tr0 = rt * TR;
    int sr  = tid % BR;                       // staging row
    int kq0 = tid / BR;                       // staging k-quad base

    // load W once
    for (int i = tid; i < Fin * N3 / 4; i += 256)
        *reinterpret_cast<float4*>(Ws + i * 4) =
            *reinterpret_cast<const float4*>(Wc + i * 4);
    __syncthreads();

    for (int chunk = blockIdx.x; chunk < NCHK; chunk += gridDim.x) {
        int row0 = chunk * BR;
        const float* xbase = X + (size_t)min(row0 + sr, NN - 1) * Fin;

        unsigned long long acc[PAIRS][TC];
#pragma unroll
        for (int p = 0; p < PAIRS; p++)
#pragma unroll
            for (int c = 0; c < TC; c++) acc[p][c] = 0ull;

        float4 xreg[PER];
#pragma unroll
        for (int q = 0; q < PER; q++)
            xreg[q] = *reinterpret_cast<const float4*>(
                xbase + (kq0 + q * (256 / BR)) * 4);

#pragma unroll
        for (int ki = 0; ki < KS; ki++) {
            float* Xb = Xs + (ki & 1) * (16 * BR);
#pragma unroll
            for (int q = 0; q < PER; q++) {
                int kq = kq0 + q * (256 / BR);
                Xb[(kq * 4 + 0) * BR + sr] = xreg[q].x;
                Xb[(kq * 4 + 1) * BR + sr] = xreg[q].y;
                Xb[(kq * 4 + 2) * BR + sr] = xreg[q].z;
                Xb[(kq * 4 + 3) * BR + sr] = xreg[q].w;
            }
            if (ki + 1 < KS) {   // prefetch next slab (hidden under compute)
#pragma unroll
                for (int q = 0; q < PER; q++)
                    xreg[q] = *reinterpret_cast<const float4*>(
                        xbase + (ki + 1) * 16 + (kq0 + q * (256 / BR)) * 4);
            }
            __syncthreads();     // single barrier per slab

            const float* Wk = Ws + ki * 16 * N3 + ct;

            // ---- software-pipelined kk loop (double reg buffer) ----
            float wv[2][TC];
            unsigned long long xp[2][PAIRS];
#pragma unroll
            for (int c = 0; c < TC; c++) wv[0][c] = Wk[c * CT];
            {
                const float* xrow = Xb + tr0;
                ulonglong2 a = *reinterpret_cast<const ulonglong2*>(xrow);
                ulonglong2 b = *reinterpret_cast<const ulonglong2*>(xrow + 4);
                xp[0][0] = a.x; xp[0][1] = a.y; xp[0][2] = b.x; xp[0][3] = b.y;
            }
#pragma unroll
            for (int kk = 0; kk < 16; kk++) {
                int cur = kk & 1, nxt = cur ^ 1;
                if (kk + 1 < 16) {
#pragma unroll
                    for (int c = 0; c < TC; c++)
                        wv[nxt][c] = Wk[(kk + 1) * N3 + c * CT];
                    const float* xrow = Xb + (kk + 1) * BR + tr0;
                    ulonglong2 a = *reinterpret_cast<const ulonglong2*>(xrow);
                    ulonglong2 b = *reinterpret_cast<const ulonglong2*>(xrow + 4);
                    xp[nxt][0] = a.x; xp[nxt][1] = a.y;
                    xp[nxt][2] = b.x; xp[nxt][3] = b.y;
                }
#pragma unroll
                for (int c = 0; c < TC; c++) {
                    unsigned long long wd = dup2(wv[cur][c]);
#pragma unroll
                    for (int p = 0; p < PAIRS; p++)
                        acc[p][c] = ffma2(xp[cur][p], wd, acc[p][c]);
                }
            }
        }

#pragma unroll
        for (int p = 0; p < PAIRS; p++) {
            int row = row0 + tr0 + 2 * p;
            float lo[TC], hi[TC];
#pragma unroll
            for (int c = 0; c < TC; c++) unpack2(acc[p][c], lo[c], hi[c]);
            if (row < NN) {
#pragma unroll
                for (int c = 0; c < TC; c++)
                    ZC[(size_t)row * N3 + c * CT + ct] = lo[c];
            }
            if (row + 1 < NN) {
#pragma unroll
                for (int c = 0; c < TC; c++)
                    ZC[(size_t)(row + 1) * N3 + c * CT + ct] = hi[c];
            }
        }
    }
}

// ---------------- props: one warp per node, unroll-2 edge loop (MLP=2) -----
// prop A: S = Z1 + 2 * (L_hat @ Z2)   (Z sections strided)
template <int F>
__global__ void k_propA(const float* __restrict__ Xg, int xs,
                        const float* __restrict__ Z1n, int zs,
                        float* __restrict__ S) {
    constexpr int LPN = F / 4;
    constexpr int EPW = 32 / LPN;
    int warp = (blockIdx.x * blockDim.x + threadIdx.x) >> 5;
    if (warp >= NN) return;
    int lane = threadIdx.x & 31;
    int sub = lane / LPN, fl = lane % LPN;
    int beg = g_rowptr[warp], end = g_rowptr[warp + 1];

    float4 a0 = make_float4(0.f, 0.f, 0.f, 0.f);
    float4 a1 = make_float4(0.f, 0.f, 0.f, 0.f);
    int idx = beg + sub;
    for (; idx + EPW < end; idx += 2 * EPW) {
        int s0 = g_csr_src[idx],       s1 = g_csr_src[idx + EPW];
        float w0 = g_csr_w[idx],       w1 = g_csr_w[idx + EPW];
        float4 x0 = *reinterpret_cast<const float4*>(Xg + (size_t)s0 * xs + fl * 4);
        float4 x1 = *reinterpret_cast<const float4*>(Xg + (size_t)s1 * xs + fl * 4);
        a0.x += w0 * x0.x; a0.y += w0 * x0.y; a0.z += w0 * x0.z; a0.w += w0 * x0.w;
        a1.x += w1 * x1.x; a1.y += w1 * x1.y; a1.z += w1 * x1.z; a1.w += w1 * x1.w;
    }
    if (idx < end) {
        int s0 = g_csr_src[idx];
        float w0 = g_csr_w[idx];
        float4 x0 = *reinterpret_cast<const float4*>(Xg + (size_t)s0 * xs + fl * 4);
        a0.x += w0 * x0.x; a0.y += w0 * x0.y; a0.z += w0 * x0.z; a0.w += w0 * x0.w;
    }
    float4 acc;
    acc.x = a0.x + a1.x; acc.y = a0.y + a1.y;
    acc.z = a0.z + a1.z; acc.w = a0.w + a1.w;
#pragma unroll
    for (int off = 16; off >= LPN; off >>= 1) {
        acc.x += __shfl_down_sync(0xffffffffu, acc.x, off);
        acc.y += __shfl_down_sync(0xffffffffu, acc.y, off);
        acc.z += __shfl_down_sync(0xffffffffu, acc.z, off);
        acc.w += __shfl_down_sync(0xffffffffu, acc.w, off);
    }
    if (sub == 0) {
        float4 z = *reinterpret_cast<const float4*>(Z1n + (size_t)warp * zs + fl * 4);
        float4 o;
        o.x = z.x + 2.f * acc.x; o.y = z.y + 2.f * acc.y;
        o.z = z.z + 2.f * acc.z; o.w = z.w + 2.f * acc.w;
        *reinterpret_cast<float4*>(S + (size_t)warp * F + fl * 4) = o;
    }
}

// prop B: H = lrelu( (Z0 + L_hat @ S) * scale + shift )
template <int F>
__global__ void k_propB(const float* __restrict__ Xg, int xs,
                        const float* __restrict__ Z0n, int zs,
                        const float* __restrict__ scale, const float* __restrict__ shift,
                        float* __restrict__ H) {
    constexpr int LPN = F / 4;
    constexpr int EPW = 32 / LPN;
    int warp = (blockIdx.x * blockDim.x + threadIdx.x) >> 5;
    if (warp >= NN) return;
    int lane = threadIdx.x & 31;
    int sub = lane / LPN, fl = lane % LPN;
    int beg = g_rowptr[warp], end = g_rowptr[warp + 1];

    float4 a0 = make_float4(0.f, 0.f, 0.f, 0.f);
    float4 a1 = make_float4(0.f, 0.f, 0.f, 0.f);
    int idx = beg + sub;
    for (; idx + EPW < end; idx += 2 * EPW) {
        int s0 = g_csr_src[idx],       s1 = g_csr_src[idx + EPW];
        float w0 = g_csr_w[idx],       w1 = g_csr_w[idx + EPW];
        float4 x0 = *reinterpret_cast<const float4*>(Xg + (size_t)s0 * xs + fl * 4);
        float4 x1 = *reinterpret_cast<const float4*>(Xg + (size_t)s1 * xs + fl * 4);
        a0.x += w0 * x0.x; a0.y += w0 * x0.y; a0.z += w0 * x0.z; a0.w += w0 * x0.w;
        a1.x += w1 * x1.x; a1.y += w1 * x1.y; a1.z += w1 * x1.z; a1.w += w1 * x1.w;
    }
    if (idx < end) {
        int s0 = g_csr_src[idx];
        float w0 = g_csr_w[idx];
        float4 x0 = *reinterpret_cast<const float4*>(Xg + (size_t)s0 * xs + fl * 4);
        a0.x += w0 * x0.x; a0.y += w0 * x0.y; a0.z += w0 * x0.z; a0.w += w0 * x0.w;
    }
    float4 acc;
    acc.x = a0.x + a1.x; acc.y = a0.y + a1.y;
    acc.z = a0.z + a1.z; acc.w = a0.w + a1.w;
#pragma unroll
    for (int off = 16; off >= LPN; off >>= 1) {
        acc.x += __shfl_down_sync(0xffffffffu, acc.x, off);
        acc.y += __shfl_down_sync(0xffffffffu, acc.y, off);
        acc.z += __shfl_down_sync(0xffffffffu, acc.z, off);
        acc.w += __shfl_down_sync(0xffffffffu, acc.w, off);
    }
    if (sub == 0) {
        float4 z  = *reinterpret_cast<const float4*>(Z0n + (size_t)warp * zs + fl * 4);
        float4 sc = *reinterpret_cast<const float4*>(scale + fl * 4);
        float4 sh = *reinterpret_cast<const float4*>(shift + fl * 4);
        float4 o;
        o.x = (z.x + acc.x) * sc.x + sh.x;
        o.y = (z.y + acc.y) * sc.y + sh.y;
        o.z = (z.z + acc.z) * sc.z + sh.z;
        o.w = (z.w + acc.w) * sc.w + sh.w;
        o.x = (o.x > 0.f) ? o.x : SLOPE * o.x;
        o.y = (o.y > 0.f) ? o.y : SLOPE * o.y;
        o.z = (o.z > 0.f) ? o.z : SLOPE * o.z;
        o.w = (o.w > 0.f) ? o.w : SLOPE * o.w;
        *reinterpret_cast<float4*>(H + (size_t)warp * F + fl * 4) = o;
    }
}

// ---------------- per-graph mean pool + head --------------------------------
#define PNODES 1024
__global__ void k_pool(const float* __restrict__ H, const int* __restrict__ batch) {
    __shared__ float ssum[GG * 16];
    __shared__ int   scnt[GG];
    for (int i = threadIdx.x; i < GG * 16; i += 256) ssum[i] = 0.f;
    for (int i = threadIdx.x; i < GG; i += 256) scnt[i] = 0;
    __syncthreads();

    int f   = threadIdx.x & 15;
    int sub = threadIdx.x >> 4;
    int base = blockIdx.x * PNODES;
    for (int n = sub; n < PNODES; n += 16) {
        int node = base + n;
        if (node >= NN) break;
        int b = batch[node];
        atomicAdd(&ssum[b * 16 + f], H[node * 16 + f]);
        if (f == 0) atomicAdd(&scnt[b], 1);
    }
    __syncthreads();
    for (int i = threadIdx.x; i < GG * 16; i += 256) atomicAdd(&g_pooled[i], ssum[i]);
    for (int i = threadIdx.x; i < GG; i += 256) atomicAdd(&g_pcnt[i], scnt[i]);
}

__global__ void k_final(const float* __restrict__ lw, const float* __restrict__ lb,
                        float* __restrict__ out) {
    int t = threadIdx.x;
    if (t >= GG * 2) return;
    int g = t >> 1, c = t & 1;
    float inv = 1.f / fmaxf((float)g_pcnt[g], 1.f);
    float s = 0.f;
#pragma unroll
    for (int f = 0; f < 16; f++) s += g_pooled[g * 16 + f] * lw[c * 16 + f];
    out[t] = s * inv + lb[c];
}

// ---------------- launch ----------------------------------------------------
extern "C" void kernel_launch(void* const* d_in, const int* in_sizes, int n_in,
                              void* d_out, int out_size) {
    const float* x     = (const float*)d_in[0];
    const int*   ei    = (const int*)  d_in[1];
    const int*   batch = (const int*)  d_in[2];
    const float* W1 = (const float*)d_in[3];
    const float* b1 = (const float*)d_in[4];
    const float* g1 = (const float*)d_in[5];
    const float* be1= (const float*)d_in[6];
    const float* m1 = (const float*)d_in[7];
    const float* v1 = (const float*)d_in[8];
    const float* W2 = (const float*)d_in[9];
    const float* b2 = (const float*)d_in[10];
    const float* g2 = (const float*)d_in[11];
    const float* be2= (const float*)d_in[12];
    const float* m2 = (const float*)d_in[13];
    const float* v2 = (const float*)d_in[14];
    const float* W3 = (const float*)d_in[15];
    const float* b3 = (const float*)d_in[16];
    const float* g3 = (const float*)d_in[17];
    const float* be3= (const float*)d_in[18];
    const float* m3 = (const float*)d_in[19];
    const float* v3 = (const float*)d_in[20];
    const float* lw = (const float*)d_in[21];
    const float* lb = (const float*)d_in[22];
    float* out = (float*)d_out;

    float *ZC, *S, *H1, *H2, *H3, *Wc1, *Wc2, *Wc3;
    float *sc1, *sh1, *sc2, *sh2, *sc3, *sh3;
    cudaGetSymbolAddress((void**)&ZC, g_ZC);
    cudaGetSymbolAddress((void**)&S,  g_S);
    cudaGetSymbolAddress((void**)&H1, g_H1);
    cudaGetSymbolAddress((void**)&H2, g_H2);
    cudaGetSymbolAddress((void**)&H3, g_H3);
    cudaGetSymbolAddress((void**)&Wc1, g_Wc1);
    cudaGetSymbolAddress((void**)&Wc2, g_Wc2);
    cudaGetSymbolAddress((void**)&Wc3, g_Wc3);
    cudaGetSymbolAddress((void**)&sc1, g_sc1);
    cudaGetSymbolAddress((void**)&sh1, g_sh1);
    cudaGetSymbolAddress((void**)&sc2, g_sc2);
    cudaGetSymbolAddress((void**)&sh2, g_sh2);
    cudaGetSymbolAddress((void**)&sc3, g_sc3);
    cudaGetSymbolAddress((void**)&sh3, g_sh3);

    // dynamic smem: W resident + 2 x (16 x BR) X slabs
    const int smem1 = (128 * 192 + 2 * 16 * 64) * 4;    // 104 KB (BR=64)
    const int smem2 = (64 * 96 + 2 * 16 * 128) * 4;     //  40 KB (BR=128)
    const int smem3 = (32 * 48 + 2 * 16 * 256) * 4;     //  38 KB (BR=256)
    cudaFuncSetAttribute((const void*)k_gemm<128, 64, 32, 64>,
                         cudaFuncAttributeMaxDynamicSharedMemorySize, smem1);
    cudaFuncSetAttribute((const void*)k_gemm<64, 32, 16, 128>,
                         cudaFuncAttributeMaxDynamicSharedMemorySize, smem2);
    cudaFuncSetAttribute((const void*)k_gemm<32, 16, 8, 256>,
                         cudaFuncAttributeMaxDynamicSharedMemorySize, smem3);

    const int TB = 256;
    const int GEMM_GRID = 296;   // quasi-persistent: 2 blocks per SM
    // launches 1-3: prelude (CSR-independent)
    k_zero <<<(NN + TB - 1) / TB, TB>>>();
    k_count<<<(EE + TB - 1) / TB, TB>>>(ei);
    k_prep <<<(24576 + 6144 + 1536 + 112 + TB - 1) / TB, TB>>>(
        W1, W2, W3, b1, g1, be1, m1, v1, b2, g2, be2, m2, v2, b3, g3, be3, m3, v3);

    // launch 4: layer-1 GEMM (profiled by ncu)
    k_gemm<128, 64, 32, 64><<<GEMM_GRID, 256, smem1>>>(x, Wc1, ZC);

    // CSR build (dinv fused into scan1)
    k_scan1<<<NB_SCAN, 1024>>>();
    k_scan2<<<1, 128>>>(NB_SCAN);
    k_scan3<<<(NN + TB - 1) / TB, TB>>>(NB_SCAN);
    k_fill <<<(EE + TB - 1) / TB, TB>>>(ei);

    int prop_grid = (NN * 32 + TB - 1) / TB;   // one warp per node

    // --- layer 1 props (sections of ZC: stride 192, offsets 0/64/128) ---
    k_propA<64><<<prop_grid, TB>>>(ZC + 128, 192, ZC + 64, 192, S);
    k_propB<64><<<prop_grid, TB>>>(S, 64, ZC, 192, sc1, sh1, H1);

    // --- layer 2: 64 -> 32 ---
    k_gemm<64, 32, 16, 128><<<GEMM_GRID, 256, smem2>>>(H1, Wc2, ZC);
    k_propA<32><<<prop_grid, TB>>>(ZC + 64, 96, ZC + 32, 96, S);
    k_propB<32><<<prop_grid, TB>>>(S, 32, ZC, 96, sc2, sh2, H2);

    // --- layer 3: 32 -> 16 ---
    k_gemm<32, 16, 8, 256><<<GEMM_GRID, 256, smem3>>>(H2, Wc3, ZC);
    k_propA<16><<<prop_grid, TB>>>(ZC + 32, 48, ZC + 16, 48, S);
    k_propB<16><<<prop_grid, TB>>>(S, 16, ZC, 48, sc3, sh3, H3);

    // --- pool + linear head ---
    k_pool <<<(NN + PNODES - 1) / PNODES, 256>>>(H3, batch);
    k_final<<<1, 128>>>(lw, lb, out);
}